// round 1
// baseline (speedup 1.0000x reference)
#include <cuda_runtime.h>
#include <math.h>

#define SZ_LOG 25
#define SZ (1u << SZ_LOG)          // 33554432
#define FD 30000000u               // FLAT_DIM
#define LOW_TILE 8192              // 2^13, low-pass tile
#define HI_C 8                     // columns per high-pass tile
#define HI_SMEM_FLOATS 33280       // 4096*8 + 64*8 padding

// Scratch (allocation-free rule: static __device__ arrays)
__device__ float g_buf0[SZ];
__device__ float g_buf1[SZ];

// ---------------------------------------------------------------------------
// Fully-unrolled in-register FWHT over 64 floats (6 butterfly stages)
// ---------------------------------------------------------------------------
__device__ __forceinline__ void fwht64(float* v) {
#pragma unroll
    for (int h = 1; h < 64; h <<= 1) {
#pragma unroll
        for (int s = 0; s < 64; s += 2 * h) {
#pragma unroll
            for (int k = 0; k < h; k++) {
                float a = v[s + k];
                float b = v[s + k + h];
                v[s + k]     = a + b;
                v[s + k + h] = a - b;
            }
        }
    }
}

// Shared-memory swizzle for the low-pass tile: XOR high bits into bank bits.
__device__ __forceinline__ int swl(int e) { return e ^ ((e >> 7) & 31); }

// ---------------------------------------------------------------------------
// Low pass: butterflies on bits 0..12 of the element index, over contiguous
// 8192-element tiles. MODE 0: x = pad(theta)*B (FWHT1 front).
//                     MODE 1: x = src[Pi[i]]*G[i] (gather + FWHT2 front).
// Phase A: bits 7..12 in registers (thread owns e = j*128 + t, coalesced).
// Phase B: bits 0..5  in registers (via shared exchange).
// Final:   bit 6 computed during the coalesced global write.
// ---------------------------------------------------------------------------
template <int MODE>
__global__ __launch_bounds__(128) void k_low(
    const float* __restrict__ theta, const float* __restrict__ Bv,
    const float* __restrict__ src,   const int*   __restrict__ Pi,
    const float* __restrict__ G,     float*       __restrict__ dst)
{
    __shared__ float s[LOW_TILE];
    const int t = threadIdx.x;                       // 0..127
    const unsigned base = blockIdx.x * LOW_TILE;

    float v[64];
#pragma unroll
    for (int j = 0; j < 64; j++) {
        unsigned idx = base + (unsigned)j * 128u + (unsigned)t;
        float x;
        if (MODE == 0) {
            float th = (idx < FD) ? theta[idx] : 0.0f;
            x = th * Bv[idx];
        } else {
            x = __ldg(&src[Pi[idx]]) * G[idx];
        }
        v[j] = x;
    }

    fwht64(v);  // bits 7..12

#pragma unroll
    for (int j = 0; j < 64; j++) s[swl(j * 128 + t)] = v[j];
    __syncthreads();

    const int b6 = t >> 6;      // bit 6 owner
    const int hi = t & 63;      // bits 7..12 owner
#pragma unroll
    for (int i = 0; i < 64; i++) v[i] = s[swl(hi * 128 + b6 * 64 + i)];

    fwht64(v);  // bits 0..5

    __syncthreads();
#pragma unroll
    for (int i = 0; i < 64; i++) s[swl(hi * 128 + b6 * 64 + i)] = v[i];
    __syncthreads();

    // Final stage (bit 6) fused with coalesced store: e = i*128 + t
#pragma unroll
    for (int i = 0; i < 64; i++) {
        int e = i * 128 + t;
        float a = s[swl(e & ~64)];
        float b = s[swl(e |  64)];
        dst[base + (unsigned)e] = (e & 64) ? (a - b) : (a + b);
    }
}

// ---------------------------------------------------------------------------
// High pass: butterflies on bits 13..24 (m = idx >> 13, 12 bits) done in ONE
// global round-trip. Tile = all 4096 m values x 8 consecutive low columns.
// Phase 1: m bits 0..5 in registers; Phase 2: m bits 6..11 in registers.
// Padded shared layout keeps every access conflict-free.
// FINAL=1: truncate to FD and apply 1/(divisor*sqrt(FD/SZ)).
// ---------------------------------------------------------------------------
__device__ __forceinline__ int sph(int m, int c) {
    return m * 8 + c + ((m >> 6) << 3);
}

template <int FINAL>
__global__ __launch_bounds__(512) void k_high(
    const float* __restrict__ src, float* __restrict__ dst,
    const float* __restrict__ divisor)
{
    extern __shared__ float sh[];
    const int t = threadIdx.x;                       // 0..511
    const unsigned low_base = blockIdx.x * HI_C;

    float v[64];
    {
        const int m_hi = t >> 3, c = t & 7;
#pragma unroll
        for (int i = 0; i < 64; i++) {
            int m = m_hi * 64 + i;
            v[i] = src[(unsigned)m * 8192u + low_base + (unsigned)c];
        }
        fwht64(v);  // m bits 0..5  (global bits 13..18)
#pragma unroll
        for (int i = 0; i < 64; i++) sh[sph(m_hi * 64 + i, c)] = v[i];
    }
    __syncthreads();
    {
        const int m_lo = t >> 3, c = t & 7;
#pragma unroll
        for (int i = 0; i < 64; i++) v[i] = sh[sph(i * 64 + m_lo, c)];

        fwht64(v);  // m bits 6..11 (global bits 19..24)

        float scale = 1.0f;
        if (FINAL)
            scale = 1.0f / (divisor[0] * sqrtf((float)FD / (float)SZ));

#pragma unroll
        for (int i = 0; i < 64; i++) {
            int m = i * 64 + m_lo;
            unsigned idx = (unsigned)m * 8192u + low_base + (unsigned)c;
            if (FINAL) {
                if (idx < FD) dst[idx] = v[i] * scale;
            } else {
                dst[idx] = v[i];
            }
        }
    }
}

// ---------------------------------------------------------------------------
// kernel_launch: 4 graph-capturable launches, no allocs, no syncs.
// ---------------------------------------------------------------------------
extern "C" void kernel_launch(void* const* d_in, const int* in_sizes, int n_in,
                              void* d_out, int out_size)
{
    const float* theta   = (const float*)d_in[0];
    const float* G       = (const float*)d_in[1];
    const float* B       = (const float*)d_in[2];
    const float* divisor = (const float*)d_in[3];
    const int*   Pi      = (const int*)d_in[4];
    float*       out     = (float*)d_out;

    float *buf0, *buf1;
    cudaGetSymbolAddress((void**)&buf0, g_buf0);
    cudaGetSymbolAddress((void**)&buf1, g_buf1);

    const int smem_hi = HI_SMEM_FLOATS * (int)sizeof(float);  // 133120 B
    cudaFuncSetAttribute(k_high<0>, cudaFuncAttributeMaxDynamicSharedMemorySize, smem_hi);
    cudaFuncSetAttribute(k_high<1>, cudaFuncAttributeMaxDynamicSharedMemorySize, smem_hi);

    const int low_grid  = SZ / LOW_TILE;   // 4096
    const int high_grid = 8192 / HI_C;     // 1024

    // FWHT #1: (pad*B fused) low bits, then high bits in-place.
    k_low<0><<<low_grid, 128>>>(theta, B, nullptr, nullptr, nullptr, buf0);
    k_high<0><<<high_grid, 512, smem_hi>>>(buf0, buf0, nullptr);

    // FWHT #2: (gather via Pi, *G fused) low bits, then high bits + scale/truncate.
    k_low<1><<<low_grid, 128>>>(nullptr, nullptr, buf0, Pi, G, buf1);
    k_high<1><<<high_grid, 512, smem_hi>>>(buf1, out, divisor);
}